// round 13
// baseline (speedup 1.0000x reference)
#include <cuda_runtime.h>
#include <math.h>
#include <stdint.h>

#define NB      4
#define IN_CHAN 128
#define HW      3136
#define HWP     3328      // 26*128 = 13*256 = 52*64
#define OC      32
#define QC      8
#define D       16
#define JSPLIT  14
#define JLEN    (HW / JSPLIT)   // 224
#define TJ      32
#define NT      (JLEN / TJ)     // 7 tiles
#define BN_EPS  1e-5f
#define QPIX    64
#define LOG2E   1.44269504088896340736f

#define SB_STRIDE 20      // 80B rows: 16B-aligned, conflict-free frag LDS
#define SP_STRIDE 36

// ---------------- scratch (device globals; no allocation allowed) ----------------
__device__ __align__(16) float g_A[NB][HWP][D];                 // log2e*[q+rk ; rq]
__device__ __align__(16) float g_B[NB][HWP][D];                 // [k ; q]
__device__ __align__(16) float g_V[NB][HWP][D];                 // v + rv
__device__ __align__(16) float g_pacc[JSPLIT][NB][HWP][D];      // partial sum(e^s * v)
__device__ __align__(16) float g_pl[JSPLIT][NB][HWP];           // partial sum(e^s)

// ---------------- helpers ----------------
__device__ __forceinline__ uint32_t f2tf(float f) {
    uint32_t r; asm("cvt.rna.tf32.f32 %0, %1;" : "=r"(r) : "f"(f)); return r;
}
__device__ __forceinline__ float ex2f(float x) {
    float r; asm("ex2.approx.ftz.f32 %0, %1;" : "=f"(r) : "f"(x)); return r;
}
__device__ __forceinline__ void mma8(float* d, const uint32_t* a, const uint32_t* b) {
    asm("mma.sync.aligned.m16n8k8.row.col.f32.tf32.tf32.f32 "
        "{%0,%1,%2,%3}, {%4,%5,%6,%7}, {%8,%9}, {%0,%1,%2,%3};"
        : "+f"(d[0]), "+f"(d[1]), "+f"(d[2]), "+f"(d[3])
        : "r"(a[0]), "r"(a[1]), "r"(a[2]), "r"(a[3]), "r"(b[0]), "r"(b[1]));
}
__device__ __forceinline__ void tfsplit(float x, uint32_t& hi, uint32_t& lo) {
    hi = f2tf(x);
    lo = f2tf(x - __uint_as_float(hi));
}
__device__ __forceinline__ void cpasync16(uint32_t saddr, const void* g) {
    asm volatile("cp.async.cg.shared.global [%0], [%1], 16;" :: "r"(saddr), "l"(g));
}
__device__ __forceinline__ void cpasync_commit() {
    asm volatile("cp.async.commit_group;" ::: "memory");
}
__device__ __forceinline__ void cpasync_wait1() {
    asm volatile("cp.async.wait_group 1;" ::: "memory");
}
__device__ __forceinline__ void cpasync_wait0() {
    asm volatile("cp.async.wait_group 0;" ::: "memory");
}

// ======================================================================
// Kernel 1: QKV 1x1 conv + BN + build A/B/V (unchanged R11/R12, 15.8us).
// ======================================================================
__global__ __launch_bounds__(256)
void qkv_kernel(const float* __restrict__ x, const float* __restrict__ w,
                const float* __restrict__ bq, const float* __restrict__ gamma,
                const float* __restrict__ beta, const float* __restrict__ mean,
                const float* __restrict__ var,
                const float* __restrict__ rq, const float* __restrict__ rk,
                const float* __restrict__ rv)
{
    __shared__ float sx[IN_CHAN][QPIX];
    __shared__ float sw[IN_CHAN][OC];
    __shared__ float srk[QC][QPIX];
    __shared__ float srq[QC][QPIX];
    __shared__ float srv[2 * QC][QPIX];
    __shared__ float sscale[OC], sbias[OC];
    __shared__ float sr[QPIX][OC + 1];

    const int tid = threadIdx.x;
    const int p   = tid & (QPIX - 1);
    const int qd  = tid >> 6;

    const int n    = blockIdx.y;
    const int pix0 = blockIdx.x * QPIX;
    const bool live = (pix0 < HW);

    if (live) {
        const float* xb = x + (size_t)n * IN_CHAN * HW + pix0;
        #pragma unroll
        for (int k = 0; k < 8; k++) {
            int i = k * 256 + tid;
            int c = i >> 4, j = (i & 15) * 4;
            cpasync16((uint32_t)__cvta_generic_to_shared(&sx[c][j]),
                      xb + (size_t)c * HW + j);
        }
        #pragma unroll
        for (int k = 0; k < 2; k++) {
            int i = k * 256 + tid;
            int row = i >> 4, j = (i & 15) * 4;
            const float* gsrc;
            float* sdst;
            if (row < 8)       { gsrc = rk + (size_t)row * HW + pix0 + j;        sdst = &srk[row][j]; }
            else if (row < 16) { gsrc = rq + (size_t)(row - 8) * HW + pix0 + j;  sdst = &srq[row - 8][j]; }
            else               { gsrc = rv + (size_t)(row - 16) * HW + pix0 + j; sdst = &srv[row - 16][j]; }
            cpasync16((uint32_t)__cvta_generic_to_shared(sdst), gsrc);
        }
    }

    for (int idx = tid; idx < IN_CHAN * OC; idx += 256) {
        int o = idx & (OC - 1), c = idx >> 5;
        sw[c][o] = w[o * IN_CHAN + c];
    }
    if (tid < OC) {
        float sc = gamma[tid] * rsqrtf(var[tid] + BN_EPS);
        sscale[tid] = sc;
        sbias[tid]  = (bq[tid] - mean[tid]) * sc + beta[tid];
    }

    if (live) { cpasync_commit(); cpasync_wait0(); }
    __syncthreads();

    if (live) {
        const int obase = qd * 8;
        float acc[8];
        #pragma unroll
        for (int k = 0; k < 8; k++) acc[k] = 0.f;

        #pragma unroll 4
        for (int c = 0; c < IN_CHAN; c++) {
            const float xs = sx[c][p];
            float4 wa = *reinterpret_cast<const float4*>(&sw[c][obase]);
            float4 wb = *reinterpret_cast<const float4*>(&sw[c][obase + 4]);
            acc[0] = fmaf(xs, wa.x, acc[0]);
            acc[1] = fmaf(xs, wa.y, acc[1]);
            acc[2] = fmaf(xs, wa.z, acc[2]);
            acc[3] = fmaf(xs, wa.w, acc[3]);
            acc[4] = fmaf(xs, wb.x, acc[4]);
            acc[5] = fmaf(xs, wb.y, acc[5]);
            acc[6] = fmaf(xs, wb.z, acc[6]);
            acc[7] = fmaf(xs, wb.w, acc[7]);
        }
        #pragma unroll
        for (int k = 0; k < 8; k++)
            sr[p][obase + k] = fmaf(acc[k], sscale[obase + k], sbias[obase + k]);
    }
    __syncthreads();

    const int gpix = pix0 + p;
    if (live) {
        if (qd == 0) {
            float av[8];
            #pragma unroll
            for (int c = 0; c < 8; c++)
                av[c] = LOG2E * (sr[p][c] + srk[c][p]);
            reinterpret_cast<float4*>(&g_A[n][gpix][0])[0] = reinterpret_cast<float4*>(av)[0];
            reinterpret_cast<float4*>(&g_A[n][gpix][0])[1] = reinterpret_cast<float4*>(av)[1];
        } else if (qd == 1) {
            float av[8];
            #pragma unroll
            for (int c = 0; c < 8; c++)
                av[c] = LOG2E * srq[c][p];
            reinterpret_cast<float4*>(&g_A[n][gpix][8])[0] = reinterpret_cast<float4*>(av)[0];
            reinterpret_cast<float4*>(&g_A[n][gpix][8])[1] = reinterpret_cast<float4*>(av)[1];
        } else if (qd == 2) {
            float bv[16];
            #pragma unroll
            for (int c = 0; c < 8; c++) { bv[c] = sr[p][QC + c]; bv[QC + c] = sr[p][c]; }
            #pragma unroll
            for (int q4 = 0; q4 < 4; q4++)
                reinterpret_cast<float4*>(&g_B[n][gpix][0])[q4] = reinterpret_cast<float4*>(bv)[q4];
        } else {
            float vv[16];
            #pragma unroll
            for (int c = 0; c < 16; c++)
                vv[c] = sr[p][2 * QC + c] + srv[c][p];
            #pragma unroll
            for (int q4 = 0; q4 < 4; q4++)
                reinterpret_cast<float4*>(&g_V[n][gpix][0])[q4] = reinterpret_cast<float4*>(vv)[q4];
        }
    } else {
        float4 z = make_float4(0.f, 0.f, 0.f, 0.f);
        if (qd == 0) {
            reinterpret_cast<float4*>(&g_A[n][gpix][0])[0] = z;
            reinterpret_cast<float4*>(&g_A[n][gpix][0])[1] = z;
        } else if (qd == 1) {
            reinterpret_cast<float4*>(&g_A[n][gpix][8])[0] = z;
            reinterpret_cast<float4*>(&g_A[n][gpix][8])[1] = z;
        } else if (qd == 2) {
            #pragma unroll
            for (int q4 = 0; q4 < 4; q4++)
                reinterpret_cast<float4*>(&g_B[n][gpix][0])[q4] = z;
        } else {
            #pragma unroll
            for (int q4 = 0; q4 < 4; q4++)
                reinterpret_cast<float4*>(&g_V[n][gpix][0])[q4] = z;
        }
    }
}

// ======================================================================
// Kernel 2: tensor-core attention, 256 threads / 8 warps per block.
// Each warp owns ONE m16 group (16 i-rows) of the 128-row i-tile:
// ~70 regs/warp -> 2-3x more resident warps to hide the per-warp
// scores->exp->sp->AV dependency chain. cp.async 3-ring unchanged.
//   scores: tf32 x3 compensated   AV: tf32 x1, l over rounded P
// ======================================================================
__global__ __launch_bounds__(256)
void attn_kernel()
{
    __shared__ __align__(16) float sB[3][TJ][SB_STRIDE];   // raw B ring
    __shared__ __align__(16) float sV[3][TJ][SB_STRIDE];   // raw V ring
    __shared__ float sp[128][SP_STRIDE];

    const int tid   = threadIdx.x;
    const int warp  = tid >> 5;       // 0..7, owns rows [warp*16, warp*16+16)
    const int lane  = tid & 31;
    const int g     = lane >> 2;
    const int tg    = lane & 3;
    const int itile = blockIdx.x;
    const int js    = blockIdx.y;
    const int n     = blockIdx.z;
    const int i0    = itile * 128;
    const int wbase = warp * 16;
    const int jbase = js * JLEN;

    // coop tile load: 2 tiles x 128 float4 chunks = 256 -> 1 chunk/thread
    const bool ldB = (tid < 128);
    const int  lch = tid & 127;
    const int  lr  = lch >> 2;
    const int  lc4 = (lch & 3) * 4;

    // ---- persistent A fragments: one m16 group ----
    uint32_t ah[2][4], al[2][4];
    #pragma unroll
    for (int ks = 0; ks < 2; ks++)
        #pragma unroll
        for (int r = 0; r < 4; r++) {
            int row = i0 + wbase + g + ((r & 1) ? 8 : 0);
            int col = ks * 8 + tg + ((r & 2) ? 4 : 0);
            tfsplit(g_A[n][row][col], ah[ks][r], al[ks][r]);
        }

    float co[2][4];
    #pragma unroll
    for (int nt = 0; nt < 2; nt++)
        #pragma unroll
        for (int r = 0; r < 4; r++) co[nt][r] = 0.f;
    float L[2] = {0.f, 0.f};

    // ---- prolog: issue tile 0 ----
    {
        const float* src = ldB ? &g_B[n][jbase + lr][lc4] : &g_V[n][jbase + lr][lc4];
        float* dst = ldB ? &sB[0][lr][lc4] : &sV[0][lr][lc4];
        cpasync16((uint32_t)__cvta_generic_to_shared(dst), src);
        cpasync_commit();
    }

    for (int t = 0; t < NT; t++) {
        if (t + 1 < NT) {
            const int jn = jbase + (t + 1) * TJ;
            const int nb = (t + 1) % 3;
            const float* src = ldB ? &g_B[n][jn + lr][lc4] : &g_V[n][jn + lr][lc4];
            float* dst = ldB ? &sB[nb][lr][lc4] : &sV[nb][lr][lc4];
            cpasync16((uint32_t)__cvta_generic_to_shared(dst), src);
            cpasync_commit();
            cpasync_wait1();
        } else {
            cpasync_wait0();
        }
        __syncthreads();
        const int buf = t % 3;

        // ---- scores: S[16i x 32j] (x3 compensated), split at read ----
        float cs[4][4];
        #pragma unroll
        for (int nt = 0; nt < 4; nt++)
            #pragma unroll
            for (int r = 0; r < 4; r++) cs[nt][r] = 0.f;

        #pragma unroll
        for (int ks = 0; ks < 2; ks++) {
            uint32_t bh[4][2], bl[4][2];
            #pragma unroll
            for (int nt = 0; nt < 4; nt++)
                #pragma unroll
                for (int rr = 0; rr < 2; rr++)
                    tfsplit(sB[buf][nt * 8 + g][ks * 8 + tg + rr * 4],
                            bh[nt][rr], bl[nt][rr]);
            #pragma unroll
            for (int nt = 0; nt < 4; nt++) {
                mma8(cs[nt], ah[ks], bh[nt]);
                mma8(cs[nt], al[ks], bh[nt]);
                mma8(cs[nt], ah[ks], bl[nt]);
            }
        }

        // ---- exp2 -> round P -> row sums over rounded P -> stage ----
        {
            float s0 = 0.f, s1 = 0.f;
            #pragma unroll
            for (int nt = 0; nt < 4; nt++) {
                float p0 = __uint_as_float(f2tf(ex2f(cs[nt][0])));
                float p1 = __uint_as_float(f2tf(ex2f(cs[nt][1])));
                float p2 = __uint_as_float(f2tf(ex2f(cs[nt][2])));
                float p3 = __uint_as_float(f2tf(ex2f(cs[nt][3])));
                s0 += p0 + p1;
                s1 += p2 + p3;
                int r0 = wbase + g;
                int c  = nt * 8 + 2 * tg;
                *reinterpret_cast<float2*>(&sp[r0][c])     = make_float2(p0, p1);
                *reinterpret_cast<float2*>(&sp[r0 + 8][c]) = make_float2(p2, p3);
            }
            s0 += __shfl_xor_sync(0xffffffffu, s0, 1);
            s0 += __shfl_xor_sync(0xffffffffu, s0, 2);
            s1 += __shfl_xor_sync(0xffffffffu, s1, 1);
            s1 += __shfl_xor_sync(0xffffffffu, s1, 2);
            L[0] += s0;
            L[1] += s1;
        }
        __syncwarp();

        // ---- AV: co += P x V, tf32 x1 (V rounded at read) ----
        #pragma unroll
        for (int kj = 0; kj < 4; kj++) {
            uint32_t pah[4];
            #pragma unroll
            for (int r = 0; r < 4; r++) {
                int row = wbase + g + ((r & 1) ? 8 : 0);
                int col = kj * 8 + tg + ((r & 2) ? 4 : 0);
                pah[r] = __float_as_uint(sp[row][col]);
            }
            uint32_t vh[2][2];
            #pragma unroll
            for (int nt = 0; nt < 2; nt++)
                #pragma unroll
                for (int rr = 0; rr < 2; rr++)
                    vh[nt][rr] = f2tf(sV[buf][kj * 8 + tg + rr * 4][nt * 8 + g]);
            #pragma unroll
            for (int nt = 0; nt < 2; nt++)
                mma8(co[nt], pah, vh[nt]);
        }
        // ring depth 3 + top-of-loop sync covers buffer reuse
    }

    // ---- epilogue ----
    #pragma unroll
    for (int nt = 0; nt < 2; nt++) {
        int r0 = i0 + wbase + g;
        int c  = nt * 8 + 2 * tg;
        *reinterpret_cast<float2*>(&g_pacc[js][n][r0][c]) =
            make_float2(co[nt][0], co[nt][1]);
        *reinterpret_cast<float2*>(&g_pacc[js][n][r0 + 8][c]) =
            make_float2(co[nt][2], co[nt][3]);
    }
    if (tg == 0) {
        g_pl[js][n][i0 + wbase + g]     = L[0];
        g_pl[js][n][i0 + wbase + g + 8] = L[1];
    }
}

// ======================================================================
// Kernel 3: combine (unchanged).
// ======================================================================
__global__ void combine_kernel(float* __restrict__ out)
{
    const int TOT  = NB * 2 * QC * 28 * 28;
    const int gidx = blockIdx.x * blockDim.x + threadIdx.x;
    if (gidx >= TOT * 4) return;
    const int e  = gidx >> 2;
    const int px = gidx & 3;

    int pw = e % 28;
    int t  = e / 28;
    int ph = t % 28; t /= 28;
    int c  = t % (2 * QC);
    int n  = t / (2 * QC);

    const int i = (2 * ph + (px >> 1)) * 56 + 2 * pw + (px & 1);

    float num = 0.f, den = 0.f;
    #pragma unroll
    for (int s = 0; s < JSPLIT; s++) {
        num += g_pacc[s][n][i][c];
        den += g_pl[s][n][i];
    }
    float r = num / den;
    r += __shfl_xor_sync(0xffffffffu, r, 1);
    r += __shfl_xor_sync(0xffffffffu, r, 2);
    if (px == 0) out[e] = 0.25f * r;
}

// ======================================================================
extern "C" void kernel_launch(void* const* d_in, const int* in_sizes, int n_in,
                              void* d_out, int out_size)
{
    const float* x     = (const float*)d_in[0];
    const float* w     = (const float*)d_in[1];
    const float* bq    = (const float*)d_in[2];
    const float* gamma = (const float*)d_in[3];
    const float* beta  = (const float*)d_in[4];
    const float* mean  = (const float*)d_in[5];
    const float* var   = (const float*)d_in[6];
    const float* rq    = (const float*)d_in[7];
    const float* rk    = (const float*)d_in[8];
    const float* rv    = (const float*)d_in[9];
    float* out = (float*)d_out;

    dim3 g1(HWP / QPIX, NB);          // (52, 4)
    qkv_kernel<<<g1, 256>>>(x, w, bq, gamma, beta, mean, var, rq, rk, rv);

    dim3 g2(HWP / 128, JSPLIT, NB);   // (26, 14, 4)
    attn_kernel<<<g2, 256>>>();

    const int TOT = NB * 2 * QC * 28 * 28;
    combine_kernel<<<(TOT * 4 + 255) / 256, 256>>>(out);
}

// round 14
// speedup vs baseline: 1.1623x; 1.1623x over previous
#include <cuda_runtime.h>
#include <math.h>
#include <stdint.h>

#define NB      4
#define IN_CHAN 128
#define HW      3136
#define HWP     3328      // 26*128 = 13*256 = 52*64
#define OC      32
#define QC      8
#define D       16
#define JSPLIT  14
#define JLEN    (HW / JSPLIT)   // 224
#define TJ      32
#define NT      (JLEN / TJ)     // 7 tiles
#define BN_EPS  1e-5f
#define QPIX    64
#define LOG2E   1.44269504088896340736f

#define SB_STRIDE 20      // 80B rows: 16B-aligned, conflict-free frag LDS
#define SP_STRIDE 36

// ---------------- scratch (device globals; no allocation allowed) ----------------
__device__ __align__(16) float g_A[NB][HWP][D];                 // log2e*[q+rk ; rq]
__device__ __align__(16) float g_B[NB][HWP][D];                 // [k ; q]
__device__ __align__(16) float g_V[NB][HWP][D];                 // v + rv
__device__ __align__(16) float g_pacc[JSPLIT][NB][HWP][D];      // partial sum(e^s * v)
__device__ __align__(16) float g_pl[JSPLIT][NB][HWP];           // partial sum(e^s)

// ---------------- helpers ----------------
__device__ __forceinline__ uint32_t f2tf(float f) {
    uint32_t r; asm("cvt.rna.tf32.f32 %0, %1;" : "=r"(r) : "f"(f)); return r;
}
__device__ __forceinline__ float ex2f(float x) {
    float r; asm("ex2.approx.ftz.f32 %0, %1;" : "=f"(r) : "f"(x)); return r;
}
__device__ __forceinline__ void mma8(float* d, const uint32_t* a, const uint32_t* b) {
    asm("mma.sync.aligned.m16n8k8.row.col.f32.tf32.tf32.f32 "
        "{%0,%1,%2,%3}, {%4,%5,%6,%7}, {%8,%9}, {%0,%1,%2,%3};"
        : "+f"(d[0]), "+f"(d[1]), "+f"(d[2]), "+f"(d[3])
        : "r"(a[0]), "r"(a[1]), "r"(a[2]), "r"(a[3]), "r"(b[0]), "r"(b[1]));
}
__device__ __forceinline__ void tfsplit(float x, uint32_t& hi, uint32_t& lo) {
    hi = f2tf(x);
    lo = f2tf(x - __uint_as_float(hi));
}
__device__ __forceinline__ void cpasync16(uint32_t saddr, const void* g) {
    asm volatile("cp.async.cg.shared.global [%0], [%1], 16;" :: "r"(saddr), "l"(g));
}
__device__ __forceinline__ void cpasync_commit() {
    asm volatile("cp.async.commit_group;" ::: "memory");
}
__device__ __forceinline__ void cpasync_wait1() {
    asm volatile("cp.async.wait_group 1;" ::: "memory");
}
__device__ __forceinline__ void cpasync_wait0() {
    asm volatile("cp.async.wait_group 0;" ::: "memory");
}

// ======================================================================
// Kernel 1: QKV 1x1 conv + BN + build A/B/V (unchanged, 15.8us).
// ======================================================================
__global__ __launch_bounds__(256)
void qkv_kernel(const float* __restrict__ x, const float* __restrict__ w,
                const float* __restrict__ bq, const float* __restrict__ gamma,
                const float* __restrict__ beta, const float* __restrict__ mean,
                const float* __restrict__ var,
                const float* __restrict__ rq, const float* __restrict__ rk,
                const float* __restrict__ rv)
{
    __shared__ float sx[IN_CHAN][QPIX];
    __shared__ float sw[IN_CHAN][OC];
    __shared__ float srk[QC][QPIX];
    __shared__ float srq[QC][QPIX];
    __shared__ float srv[2 * QC][QPIX];
    __shared__ float sscale[OC], sbias[OC];
    __shared__ float sr[QPIX][OC + 1];

    const int tid = threadIdx.x;
    const int p   = tid & (QPIX - 1);
    const int qd  = tid >> 6;

    const int n    = blockIdx.y;
    const int pix0 = blockIdx.x * QPIX;
    const bool live = (pix0 < HW);

    if (live) {
        const float* xb = x + (size_t)n * IN_CHAN * HW + pix0;
        #pragma unroll
        for (int k = 0; k < 8; k++) {
            int i = k * 256 + tid;
            int c = i >> 4, j = (i & 15) * 4;
            cpasync16((uint32_t)__cvta_generic_to_shared(&sx[c][j]),
                      xb + (size_t)c * HW + j);
        }
        #pragma unroll
        for (int k = 0; k < 2; k++) {
            int i = k * 256 + tid;
            int row = i >> 4, j = (i & 15) * 4;
            const float* gsrc;
            float* sdst;
            if (row < 8)       { gsrc = rk + (size_t)row * HW + pix0 + j;        sdst = &srk[row][j]; }
            else if (row < 16) { gsrc = rq + (size_t)(row - 8) * HW + pix0 + j;  sdst = &srq[row - 8][j]; }
            else               { gsrc = rv + (size_t)(row - 16) * HW + pix0 + j; sdst = &srv[row - 16][j]; }
            cpasync16((uint32_t)__cvta_generic_to_shared(sdst), gsrc);
        }
    }

    for (int idx = tid; idx < IN_CHAN * OC; idx += 256) {
        int o = idx & (OC - 1), c = idx >> 5;
        sw[c][o] = w[o * IN_CHAN + c];
    }
    if (tid < OC) {
        float sc = gamma[tid] * rsqrtf(var[tid] + BN_EPS);
        sscale[tid] = sc;
        sbias[tid]  = (bq[tid] - mean[tid]) * sc + beta[tid];
    }

    if (live) { cpasync_commit(); cpasync_wait0(); }
    __syncthreads();

    if (live) {
        const int obase = qd * 8;
        float acc[8];
        #pragma unroll
        for (int k = 0; k < 8; k++) acc[k] = 0.f;

        #pragma unroll 4
        for (int c = 0; c < IN_CHAN; c++) {
            const float xs = sx[c][p];
            float4 wa = *reinterpret_cast<const float4*>(&sw[c][obase]);
            float4 wb = *reinterpret_cast<const float4*>(&sw[c][obase + 4]);
            acc[0] = fmaf(xs, wa.x, acc[0]);
            acc[1] = fmaf(xs, wa.y, acc[1]);
            acc[2] = fmaf(xs, wa.z, acc[2]);
            acc[3] = fmaf(xs, wa.w, acc[3]);
            acc[4] = fmaf(xs, wb.x, acc[4]);
            acc[5] = fmaf(xs, wb.y, acc[5]);
            acc[6] = fmaf(xs, wb.z, acc[6]);
            acc[7] = fmaf(xs, wb.w, acc[7]);
        }
        #pragma unroll
        for (int k = 0; k < 8; k++)
            sr[p][obase + k] = fmaf(acc[k], sscale[obase + k], sbias[obase + k]);
    }
    __syncthreads();

    const int gpix = pix0 + p;
    if (live) {
        if (qd == 0) {
            float av[8];
            #pragma unroll
            for (int c = 0; c < 8; c++)
                av[c] = LOG2E * (sr[p][c] + srk[c][p]);
            reinterpret_cast<float4*>(&g_A[n][gpix][0])[0] = reinterpret_cast<float4*>(av)[0];
            reinterpret_cast<float4*>(&g_A[n][gpix][0])[1] = reinterpret_cast<float4*>(av)[1];
        } else if (qd == 1) {
            float av[8];
            #pragma unroll
            for (int c = 0; c < 8; c++)
                av[c] = LOG2E * srq[c][p];
            reinterpret_cast<float4*>(&g_A[n][gpix][8])[0] = reinterpret_cast<float4*>(av)[0];
            reinterpret_cast<float4*>(&g_A[n][gpix][8])[1] = reinterpret_cast<float4*>(av)[1];
        } else if (qd == 2) {
            float bv[16];
            #pragma unroll
            for (int c = 0; c < 8; c++) { bv[c] = sr[p][QC + c]; bv[QC + c] = sr[p][c]; }
            #pragma unroll
            for (int q4 = 0; q4 < 4; q4++)
                reinterpret_cast<float4*>(&g_B[n][gpix][0])[q4] = reinterpret_cast<float4*>(bv)[q4];
        } else {
            float vv[16];
            #pragma unroll
            for (int c = 0; c < 16; c++)
                vv[c] = sr[p][2 * QC + c] + srv[c][p];
            #pragma unroll
            for (int q4 = 0; q4 < 4; q4++)
                reinterpret_cast<float4*>(&g_V[n][gpix][0])[q4] = reinterpret_cast<float4*>(vv)[q4];
        }
    } else {
        float4 z = make_float4(0.f, 0.f, 0.f, 0.f);
        if (qd == 0) {
            reinterpret_cast<float4*>(&g_A[n][gpix][0])[0] = z;
            reinterpret_cast<float4*>(&g_A[n][gpix][0])[1] = z;
        } else if (qd == 1) {
            reinterpret_cast<float4*>(&g_A[n][gpix][8])[0] = z;
            reinterpret_cast<float4*>(&g_A[n][gpix][8])[1] = z;
        } else if (qd == 2) {
            #pragma unroll
            for (int q4 = 0; q4 < 4; q4++)
                reinterpret_cast<float4*>(&g_B[n][gpix][0])[q4] = z;
        } else {
            #pragma unroll
            for (int q4 = 0; q4 < 4; q4++)
                reinterpret_cast<float4*>(&g_V[n][gpix][0])[q4] = z;
        }
    }
}

// ======================================================================
// Kernel 2: tensor-core attention (R12 structure, 4 warps x 32 i-rows)
// + __launch_bounds__(128,4) to force 4 blocks/SM (16 warps resident)
// + l row-sum shuffle reduction deferred out of the tile loop.
//   scores: tf32 x3 compensated   AV: tf32 x1, l over rounded P
// ======================================================================
__global__ __launch_bounds__(128, 4)
void attn_kernel()
{
    __shared__ __align__(16) float sB[3][TJ][SB_STRIDE];   // raw B ring
    __shared__ __align__(16) float sV[3][TJ][SB_STRIDE];   // raw V ring
    __shared__ float sp[128][SP_STRIDE];

    const int tid   = threadIdx.x;
    const int warp  = tid >> 5;
    const int lane  = tid & 31;
    const int g     = lane >> 2;
    const int tg    = lane & 3;
    const int itile = blockIdx.x;
    const int js    = blockIdx.y;
    const int n     = blockIdx.z;
    const int i0    = itile * 128;
    const int wbase = warp * 32;
    const int jbase = js * JLEN;

    const int lr  = tid >> 2;           // tile row this thread loads
    const int lc4 = (tid & 3) * 4;      // tile col (16B chunk)

    // ---- persistent A fragments ----
    uint32_t ah[2][2][4], al[2][2][4];
    #pragma unroll
    for (int mg = 0; mg < 2; mg++)
        #pragma unroll
        for (int ks = 0; ks < 2; ks++)
            #pragma unroll
            for (int r = 0; r < 4; r++) {
                int row = i0 + wbase + mg * 16 + g + ((r & 1) ? 8 : 0);
                int col = ks * 8 + tg + ((r & 2) ? 4 : 0);
                tfsplit(g_A[n][row][col], ah[mg][ks][r], al[mg][ks][r]);
            }

    float co[2][2][4];
    #pragma unroll
    for (int mg = 0; mg < 2; mg++)
        #pragma unroll
        for (int nt = 0; nt < 2; nt++)
            #pragma unroll
            for (int r = 0; r < 4; r++) co[mg][nt][r] = 0.f;
    // per-thread partial row sums; shuffle-reduced ONCE after the loop
    float L[2][2] = {{0.f, 0.f}, {0.f, 0.f}};

    // ---- prolog: issue tile 0 ----
    {
        cpasync16((uint32_t)__cvta_generic_to_shared(&sB[0][lr][lc4]),
                  &g_B[n][jbase + lr][lc4]);
        cpasync16((uint32_t)__cvta_generic_to_shared(&sV[0][lr][lc4]),
                  &g_V[n][jbase + lr][lc4]);
        cpasync_commit();
    }

    for (int t = 0; t < NT; t++) {
        if (t + 1 < NT) {
            const int jn = jbase + (t + 1) * TJ;
            const int nb = (t + 1) % 3;
            cpasync16((uint32_t)__cvta_generic_to_shared(&sB[nb][lr][lc4]),
                      &g_B[n][jn + lr][lc4]);
            cpasync16((uint32_t)__cvta_generic_to_shared(&sV[nb][lr][lc4]),
                      &g_V[n][jn + lr][lc4]);
            cpasync_commit();
            cpasync_wait1();
        } else {
            cpasync_wait0();
        }
        __syncthreads();
        const int buf = t % 3;

        // ---- scores: S[32i x 32j] per warp (x3 compensated), split at read ----
        float cs[2][4][4];
        #pragma unroll
        for (int mg = 0; mg < 2; mg++)
            #pragma unroll
            for (int nt = 0; nt < 4; nt++)
                #pragma unroll
                for (int r = 0; r < 4; r++) cs[mg][nt][r] = 0.f;

        #pragma unroll
        for (int ks = 0; ks < 2; ks++) {
            uint32_t bh[4][2], bl[4][2];
            #pragma unroll
            for (int nt = 0; nt < 4; nt++)
                #pragma unroll
                for (int rr = 0; rr < 2; rr++)
                    tfsplit(sB[buf][nt * 8 + g][ks * 8 + tg + rr * 4],
                            bh[nt][rr], bl[nt][rr]);
            #pragma unroll
            for (int mg = 0; mg < 2; mg++)
                #pragma unroll
                for (int nt = 0; nt < 4; nt++) {
                    mma8(cs[mg][nt], ah[mg][ks], bh[nt]);
                    mma8(cs[mg][nt], al[mg][ks], bh[nt]);
                    mma8(cs[mg][nt], ah[mg][ks], bl[nt]);
                }
        }

        // ---- exp2 -> round P -> accumulate per-thread partial sums -> stage ----
        #pragma unroll
        for (int mg = 0; mg < 2; mg++) {
            #pragma unroll
            for (int nt = 0; nt < 4; nt++) {
                float p0 = __uint_as_float(f2tf(ex2f(cs[mg][nt][0])));
                float p1 = __uint_as_float(f2tf(ex2f(cs[mg][nt][1])));
                float p2 = __uint_as_float(f2tf(ex2f(cs[mg][nt][2])));
                float p3 = __uint_as_float(f2tf(ex2f(cs[mg][nt][3])));
                L[mg][0] += p0 + p1;
                L[mg][1] += p2 + p3;
                int r0 = wbase + mg * 16 + g;
                int c  = nt * 8 + 2 * tg;
                *reinterpret_cast<float2*>(&sp[r0][c])     = make_float2(p0, p1);
                *reinterpret_cast<float2*>(&sp[r0 + 8][c]) = make_float2(p2, p3);
            }
        }
        __syncwarp();

        // ---- AV: co += P x V, tf32 x1 (V rounded at read) ----
        #pragma unroll
        for (int kj = 0; kj < 4; kj++) {
            uint32_t vh[2][2];
            #pragma unroll
            for (int nt = 0; nt < 2; nt++)
                #pragma unroll
                for (int rr = 0; rr < 2; rr++)
                    vh[nt][rr] = f2tf(sV[buf][kj * 8 + tg + rr * 4][nt * 8 + g]);
            uint32_t pah[2][4];
            #pragma unroll
            for (int mg = 0; mg < 2; mg++)
                #pragma unroll
                for (int r = 0; r < 4; r++) {
                    int row = wbase + mg * 16 + g + ((r & 1) ? 8 : 0);
                    int col = kj * 8 + tg + ((r & 2) ? 4 : 0);
                    pah[mg][r] = __float_as_uint(sp[row][col]);
                }
            #pragma unroll
            for (int mg = 0; mg < 2; mg++)
                #pragma unroll
                for (int nt = 0; nt < 2; nt++)
                    mma8(co[mg][nt], pah[mg], vh[nt]);
        }
        // ring depth 3 + top-of-loop sync covers buffer reuse
    }

    // ---- deferred l reduction (once instead of per tile) ----
    #pragma unroll
    for (int mg = 0; mg < 2; mg++) {
        #pragma unroll
        for (int h = 0; h < 2; h++) {
            float s = L[mg][h];
            s += __shfl_xor_sync(0xffffffffu, s, 1);
            s += __shfl_xor_sync(0xffffffffu, s, 2);
            L[mg][h] = s;
        }
    }

    // ---- epilogue ----
    #pragma unroll
    for (int mg = 0; mg < 2; mg++)
        #pragma unroll
        for (int nt = 0; nt < 2; nt++) {
            int r0 = i0 + wbase + mg * 16 + g;
            int c  = nt * 8 + 2 * tg;
            *reinterpret_cast<float2*>(&g_pacc[js][n][r0][c]) =
                make_float2(co[mg][nt][0], co[mg][nt][1]);
            *reinterpret_cast<float2*>(&g_pacc[js][n][r0 + 8][c]) =
                make_float2(co[mg][nt][2], co[mg][nt][3]);
        }
    if (tg == 0) {
        #pragma unroll
        for (int mg = 0; mg < 2; mg++) {
            g_pl[js][n][i0 + wbase + mg * 16 + g]     = L[mg][0];
            g_pl[js][n][i0 + wbase + mg * 16 + g + 8] = L[mg][1];
        }
    }
}

// ======================================================================
// Kernel 3: combine (unchanged).
// ======================================================================
__global__ void combine_kernel(float* __restrict__ out)
{
    const int TOT  = NB * 2 * QC * 28 * 28;
    const int gidx = blockIdx.x * blockDim.x + threadIdx.x;
    if (gidx >= TOT * 4) return;
    const int e  = gidx >> 2;
    const int px = gidx & 3;

    int pw = e % 28;
    int t  = e / 28;
    int ph = t % 28; t /= 28;
    int c  = t % (2 * QC);
    int n  = t / (2 * QC);

    const int i = (2 * ph + (px >> 1)) * 56 + 2 * pw + (px & 1);

    float num = 0.f, den = 0.f;
    #pragma unroll
    for (int s = 0; s < JSPLIT; s++) {
        num += g_pacc[s][n][i][c];
        den += g_pl[s][n][i];
    }
    float r = num / den;
    r += __shfl_xor_sync(0xffffffffu, r, 1);
    r += __shfl_xor_sync(0xffffffffu, r, 2);
    if (px == 0) out[e] = 0.25f * r;
}

// ======================================================================
extern "C" void kernel_launch(void* const* d_in, const int* in_sizes, int n_in,
                              void* d_out, int out_size)
{
    const float* x     = (const float*)d_in[0];
    const float* w     = (const float*)d_in[1];
    const float* bq    = (const float*)d_in[2];
    const float* gamma = (const float*)d_in[3];
    const float* beta  = (const float*)d_in[4];
    const float* mean  = (const float*)d_in[5];
    const float* var   = (const float*)d_in[6];
    const float* rq    = (const float*)d_in[7];
    const float* rk    = (const float*)d_in[8];
    const float* rv    = (const float*)d_in[9];
    float* out = (float*)d_out;

    dim3 g1(HWP / QPIX, NB);          // (52, 4)
    qkv_kernel<<<g1, 256>>>(x, w, bq, gamma, beta, mean, var, rq, rk, rv);

    dim3 g2(HWP / 128, JSPLIT, NB);   // (26, 14, 4)
    attn_kernel<<<g2, 128>>>();

    const int TOT = NB * 2 * QC * 28 * 28;
    combine_kernel<<<(TOT * 4 + 255) / 256, 256>>>(out);
}

// round 15
// speedup vs baseline: 1.3807x; 1.1879x over previous
#include <cuda_runtime.h>
#include <cuda_fp16.h>
#include <math.h>
#include <stdint.h>

#define NB      4
#define IN_CHAN 128
#define HW      3136
#define HWP     3328      // 26*128 = 13*256 = 52*64
#define OC      32
#define QC      8
#define D       16
#define JSPLIT  14
#define JLEN    (HW / JSPLIT)   // 224
#define TJ      32
#define NT      (JLEN / TJ)     // 7 tiles
#define BN_EPS  1e-5f
#define QPIX    64
#define LOG2E   1.44269504088896340736f

#define SB_STRIDE 20      // f32 tile rows, conflict-free (20g+tg distinct mod 32)
#define SP_STRIDE 20      // uint32 (f16x2) rows, conflict-free
#define VT_STRIDE 20

// ---------------- scratch (device globals; no allocation allowed) ----------------
__device__ __align__(16) float g_A[NB][HWP][D];                 // log2e*[q+rk ; rq]
__device__ __align__(16) float g_B[NB][HWP][D];                 // [k ; q]
__device__ __align__(16) float g_V[NB][HWP][D];                 // v + rv
__device__ __align__(16) float g_pacc[JSPLIT][NB][HWP][D];      // partial sum(e^s * v), 2^m-scaled back
__device__ __align__(16) float g_pl[JSPLIT][NB][HWP];           // partial sum(e^s)

// ---------------- helpers ----------------
__device__ __forceinline__ float ex2f(float x) {
    float r; asm("ex2.approx.ftz.f32 %0, %1;" : "=f"(r) : "f"(x)); return r;
}
__device__ __forceinline__ uint32_t h2_bits(__half2 h) { return *reinterpret_cast<uint32_t*>(&h); }
__device__ __forceinline__ __half2 bits_h2(uint32_t u) { return *reinterpret_cast<__half2*>(&u); }
// pack two f32 (lo first) into f16x2 bits
__device__ __forceinline__ uint32_t pack_h2(float lo, float hi) {
    __half2 h = __floats2half2_rn(lo, hi); return h2_bits(h);
}
// split f32 pair into f16 hi + f16 lo (residual) fragments
__device__ __forceinline__ void h2split(float2 v, uint32_t& hi, uint32_t& lo) {
    __half2 h = __floats2half2_rn(v.x, v.y);
    hi = h2_bits(h);
    float2 b = __half22float2(h);
    __half2 l = __floats2half2_rn(v.x - b.x, v.y - b.y);
    lo = h2_bits(l);
}
// fp16 m16n8k16 mma, f32 accumulate
__device__ __forceinline__ void mma16(float* d, const uint32_t* a, uint32_t b0, uint32_t b1) {
    asm("mma.sync.aligned.m16n8k16.row.col.f32.f16.f16.f32 "
        "{%0,%1,%2,%3}, {%4,%5,%6,%7}, {%8,%9}, {%0,%1,%2,%3};"
        : "+f"(d[0]), "+f"(d[1]), "+f"(d[2]), "+f"(d[3])
        : "r"(a[0]), "r"(a[1]), "r"(a[2]), "r"(a[3]), "r"(b0), "r"(b1));
}
__device__ __forceinline__ void cpasync16(uint32_t saddr, const void* g) {
    asm volatile("cp.async.cg.shared.global [%0], [%1], 16;" :: "r"(saddr), "l"(g));
}
__device__ __forceinline__ void cpasync_commit() {
    asm volatile("cp.async.commit_group;" ::: "memory");
}
__device__ __forceinline__ void cpasync_wait1() {
    asm volatile("cp.async.wait_group 1;" ::: "memory");
}
__device__ __forceinline__ void cpasync_wait0() {
    asm volatile("cp.async.wait_group 0;" ::: "memory");
}

// ======================================================================
// Kernel 1: QKV 1x1 conv + BN + build A/B/V (unchanged, ~15.8us).
// ======================================================================
__global__ __launch_bounds__(256)
void qkv_kernel(const float* __restrict__ x, const float* __restrict__ w,
                const float* __restrict__ bq, const float* __restrict__ gamma,
                const float* __restrict__ beta, const float* __restrict__ mean,
                const float* __restrict__ var,
                const float* __restrict__ rq, const float* __restrict__ rk,
                const float* __restrict__ rv)
{
    __shared__ float sx[IN_CHAN][QPIX];
    __shared__ float sw[IN_CHAN][OC];
    __shared__ float srk[QC][QPIX];
    __shared__ float srq[QC][QPIX];
    __shared__ float srv[2 * QC][QPIX];
    __shared__ float sscale[OC], sbias[OC];
    __shared__ float sr[QPIX][OC + 1];

    const int tid = threadIdx.x;
    const int p   = tid & (QPIX - 1);
    const int qd  = tid >> 6;

    const int n    = blockIdx.y;
    const int pix0 = blockIdx.x * QPIX;
    const bool live = (pix0 < HW);

    if (live) {
        const float* xb = x + (size_t)n * IN_CHAN * HW + pix0;
        #pragma unroll
        for (int k = 0; k < 8; k++) {
            int i = k * 256 + tid;
            int c = i >> 4, j = (i & 15) * 4;
            cpasync16((uint32_t)__cvta_generic_to_shared(&sx[c][j]),
                      xb + (size_t)c * HW + j);
        }
        #pragma unroll
        for (int k = 0; k < 2; k++) {
            int i = k * 256 + tid;
            int row = i >> 4, j = (i & 15) * 4;
            const float* gsrc;
            float* sdst;
            if (row < 8)       { gsrc = rk + (size_t)row * HW + pix0 + j;        sdst = &srk[row][j]; }
            else if (row < 16) { gsrc = rq + (size_t)(row - 8) * HW + pix0 + j;  sdst = &srq[row - 8][j]; }
            else               { gsrc = rv + (size_t)(row - 16) * HW + pix0 + j; sdst = &srv[row - 16][j]; }
            cpasync16((uint32_t)__cvta_generic_to_shared(sdst), gsrc);
        }
    }

    for (int idx = tid; idx < IN_CHAN * OC; idx += 256) {
        int o = idx & (OC - 1), c = idx >> 5;
        sw[c][o] = w[o * IN_CHAN + c];
    }
    if (tid < OC) {
        float sc = gamma[tid] * rsqrtf(var[tid] + BN_EPS);
        sscale[tid] = sc;
        sbias[tid]  = (bq[tid] - mean[tid]) * sc + beta[tid];
    }

    if (live) { cpasync_commit(); cpasync_wait0(); }
    __syncthreads();

    if (live) {
        const int obase = qd * 8;
        float acc[8];
        #pragma unroll
        for (int k = 0; k < 8; k++) acc[k] = 0.f;

        #pragma unroll 4
        for (int c = 0; c < IN_CHAN; c++) {
            const float xs = sx[c][p];
            float4 wa = *reinterpret_cast<const float4*>(&sw[c][obase]);
            float4 wb = *reinterpret_cast<const float4*>(&sw[c][obase + 4]);
            acc[0] = fmaf(xs, wa.x, acc[0]);
            acc[1] = fmaf(xs, wa.y, acc[1]);
            acc[2] = fmaf(xs, wa.z, acc[2]);
            acc[3] = fmaf(xs, wa.w, acc[3]);
            acc[4] = fmaf(xs, wb.x, acc[4]);
            acc[5] = fmaf(xs, wb.y, acc[5]);
            acc[6] = fmaf(xs, wb.z, acc[6]);
            acc[7] = fmaf(xs, wb.w, acc[7]);
        }
        #pragma unroll
        for (int k = 0; k < 8; k++)
            sr[p][obase + k] = fmaf(acc[k], sscale[obase + k], sbias[obase + k]);
    }
    __syncthreads();

    const int gpix = pix0 + p;
    if (live) {
        if (qd == 0) {
            float av[8];
            #pragma unroll
            for (int c = 0; c < 8; c++)
                av[c] = LOG2E * (sr[p][c] + srk[c][p]);
            reinterpret_cast<float4*>(&g_A[n][gpix][0])[0] = reinterpret_cast<float4*>(av)[0];
            reinterpret_cast<float4*>(&g_A[n][gpix][0])[1] = reinterpret_cast<float4*>(av)[1];
        } else if (qd == 1) {
            float av[8];
            #pragma unroll
            for (int c = 0; c < 8; c++)
                av[c] = LOG2E * srq[c][p];
            reinterpret_cast<float4*>(&g_A[n][gpix][8])[0] = reinterpret_cast<float4*>(av)[0];
            reinterpret_cast<float4*>(&g_A[n][gpix][8])[1] = reinterpret_cast<float4*>(av)[1];
        } else if (qd == 2) {
            float bv[16];
            #pragma unroll
            for (int c = 0; c < 8; c++) { bv[c] = sr[p][QC + c]; bv[QC + c] = sr[p][c]; }
            #pragma unroll
            for (int q4 = 0; q4 < 4; q4++)
                reinterpret_cast<float4*>(&g_B[n][gpix][0])[q4] = reinterpret_cast<float4*>(bv)[q4];
        } else {
            float vv[16];
            #pragma unroll
            for (int c = 0; c < 16; c++)
                vv[c] = sr[p][2 * QC + c] + srv[c][p];
            #pragma unroll
            for (int q4 = 0; q4 < 4; q4++)
                reinterpret_cast<float4*>(&g_V[n][gpix][0])[q4] = reinterpret_cast<float4*>(vv)[q4];
        }
    } else {
        float4 z = make_float4(0.f, 0.f, 0.f, 0.f);
        if (qd == 0) {
            reinterpret_cast<float4*>(&g_A[n][gpix][0])[0] = z;
            reinterpret_cast<float4*>(&g_A[n][gpix][0])[1] = z;
        } else if (qd == 1) {
            reinterpret_cast<float4*>(&g_A[n][gpix][8])[0] = z;
            reinterpret_cast<float4*>(&g_A[n][gpix][8])[1] = z;
        } else if (qd == 2) {
            #pragma unroll
            for (int q4 = 0; q4 < 4; q4++)
                reinterpret_cast<float4*>(&g_B[n][gpix][0])[q4] = z;
        } else {
            #pragma unroll
            for (int q4 = 0; q4 < 4; q4++)
                reinterpret_cast<float4*>(&g_V[n][gpix][0])[q4] = z;
        }
    }
}

// ======================================================================
// Kernel 2: fp16 m16n8k16 tensor-core attention (HALF the HMMA count).
//   scores: fp16 x3 compensated (same precision as tf32 x3)
//   softmax: online per-row max (keeps P in [0,1] for fp16);
//            epilogue multiplies partials by 2^m -> combine unchanged
//   PV: fp16 x1 (P/V 10-bit mantissa = same error as tf32 x1);
//       l summed over the SAME rounded-P values the mma uses
// cp.async 3-ring for raw f32 B/V tiles; per-tile coop f16 transpose of V.
// ======================================================================
__global__ __launch_bounds__(128, 4)
void attn_kernel()
{
    __shared__ __align__(16) float sB[3][TJ][SB_STRIDE];     // raw B ring (f32)
    __shared__ __align__(16) float sV[3][TJ][SB_STRIDE];     // raw V ring (f32)
    __shared__ uint32_t sp[128][SP_STRIDE];                  // P as f16x2 (j-pairs)
    __shared__ uint32_t sVt[D][VT_STRIDE];                   // V^T as f16x2 (j-pairs)

    const int tid   = threadIdx.x;
    const int warp  = tid >> 5;
    const int lane  = tid & 31;
    const int g     = lane >> 2;
    const int tg    = lane & 3;
    const int itile = blockIdx.x;
    const int js    = blockIdx.y;
    const int n     = blockIdx.z;
    const int i0    = itile * 128;
    const int wbase = warp * 32;
    const int jbase = js * JLEN;

    const int lr  = tid >> 2;           // ring-load row
    const int lc4 = (tid & 3) * 4;      // ring-load col chunk

    // sVt coop-build indices: thread handles (jp, dp) -> 2 d-rows
    const int vjp = tid & 15;
    const int vdp = tid >> 4;           // 0..7

    // ---- persistent A fragments (f16 hi/lo, m16n8k16 A layout) ----
    uint32_t ahh[2][4], ahl[2][4];
    #pragma unroll
    for (int mg = 0; mg < 2; mg++) {
        #pragma unroll
        for (int r = 0; r < 4; r++) {
            int row = i0 + wbase + mg * 16 + g + ((r & 1) ? 8 : 0);
            int col = 2 * tg + ((r & 2) ? 8 : 0);
            float2 a2 = *reinterpret_cast<const float2*>(&g_A[n][row][col]);
            h2split(a2, ahh[mg][r], ahl[mg][r]);
        }
    }

    float co[2][2][4];
    #pragma unroll
    for (int mg = 0; mg < 2; mg++)
        #pragma unroll
        for (int nt = 0; nt < 2; nt++)
            #pragma unroll
            for (int r = 0; r < 4; r++) co[mg][nt][r] = 0.f;
    float L[2][2]  = {{0.f, 0.f}, {0.f, 0.f}};
    float mo[2][2] = {{-1e30f, -1e30f}, {-1e30f, -1e30f}};  // running row max (log2)

    // ---- prolog: issue tile 0 ----
    {
        cpasync16((uint32_t)__cvta_generic_to_shared(&sB[0][lr][lc4]),
                  &g_B[n][jbase + lr][lc4]);
        cpasync16((uint32_t)__cvta_generic_to_shared(&sV[0][lr][lc4]),
                  &g_V[n][jbase + lr][lc4]);
        cpasync_commit();
    }

    for (int t = 0; t < NT; t++) {
        if (t + 1 < NT) {
            const int jn = jbase + (t + 1) * TJ;
            const int nb = (t + 1) % 3;
            cpasync16((uint32_t)__cvta_generic_to_shared(&sB[nb][lr][lc4]),
                      &g_B[n][jn + lr][lc4]);
            cpasync16((uint32_t)__cvta_generic_to_shared(&sV[nb][lr][lc4]),
                      &g_V[n][jn + lr][lc4]);
            cpasync_commit();
            cpasync_wait1();
        } else {
            cpasync_wait0();
        }
        __syncthreads();
        const int buf = t % 3;

        // ---- coop: build sVt[d][jp] = f16x2(V[2jp][d], V[2jp+1][d]) ----
        {
            float2 v0 = *reinterpret_cast<const float2*>(&sV[buf][2 * vjp][2 * vdp]);
            float2 v1 = *reinterpret_cast<const float2*>(&sV[buf][2 * vjp + 1][2 * vdp]);
            sVt[2 * vdp][vjp]     = pack_h2(v0.x, v1.x);
            sVt[2 * vdp + 1][vjp] = pack_h2(v0.y, v1.y);
        }
        __syncthreads();

        // ---- scores: S[32i x 32j] per warp, fp16 x3 ----
        float cs[2][4][4];
        #pragma unroll
        for (int mg = 0; mg < 2; mg++)
            #pragma unroll
            for (int nt = 0; nt < 4; nt++)
                #pragma unroll
                for (int r = 0; r < 4; r++) cs[mg][nt][r] = 0.f;

        #pragma unroll
        for (int nt = 0; nt < 4; nt++) {
            float2 q0 = *reinterpret_cast<const float2*>(&sB[buf][nt * 8 + g][2 * tg]);
            float2 q1 = *reinterpret_cast<const float2*>(&sB[buf][nt * 8 + g][2 * tg + 8]);
            uint32_t bh0, bl0, bh1, bl1;
            h2split(q0, bh0, bl0);
            h2split(q1, bh1, bl1);
            #pragma unroll
            for (int mg = 0; mg < 2; mg++) {
                mma16(cs[mg][nt], ahh[mg], bh0, bh1);
                mma16(cs[mg][nt], ahl[mg], bh0, bh1);
                mma16(cs[mg][nt], ahh[mg], bl0, bl1);
            }
        }

        // ---- online max + rescale + exp2 -> f16 P -> L over rounded P ----
        #pragma unroll
        for (int mg = 0; mg < 2; mg++) {
            // per-row tile max (row0 = g, row1 = g+8)
            float m0t = cs[mg][0][0], m1t = cs[mg][0][2];
            m0t = fmaxf(m0t, cs[mg][0][1]); m1t = fmaxf(m1t, cs[mg][0][3]);
            #pragma unroll
            for (int nt = 1; nt < 4; nt++) {
                m0t = fmaxf(m0t, fmaxf(cs[mg][nt][0], cs[mg][nt][1]));
                m1t = fmaxf(m1t, fmaxf(cs[mg][nt][2], cs[mg][nt][3]));
            }
            m0t = fmaxf(m0t, __shfl_xor_sync(0xffffffffu, m0t, 1));
            m0t = fmaxf(m0t, __shfl_xor_sync(0xffffffffu, m0t, 2));
            m1t = fmaxf(m1t, __shfl_xor_sync(0xffffffffu, m1t, 1));
            m1t = fmaxf(m1t, __shfl_xor_sync(0xffffffffu, m1t, 2));
            float m0 = fmaxf(mo[mg][0], m0t);
            float m1 = fmaxf(mo[mg][1], m1t);
            float f0 = ex2f(mo[mg][0] - m0);
            float f1 = ex2f(mo[mg][1] - m1);
            mo[mg][0] = m0; mo[mg][1] = m1;
            #pragma unroll
            for (int nt = 0; nt < 2; nt++) {
                co[mg][nt][0] *= f0; co[mg][nt][1] *= f0;
                co[mg][nt][2] *= f1; co[mg][nt][3] *= f1;
            }
            L[mg][0] *= f0; L[mg][1] *= f1;

            const int r0 = wbase + mg * 16 + g;
            #pragma unroll
            for (int nt = 0; nt < 4; nt++) {
                float e0 = ex2f(cs[mg][nt][0] - m0);
                float e1 = ex2f(cs[mg][nt][1] - m0);
                float e2 = ex2f(cs[mg][nt][2] - m1);
                float e3 = ex2f(cs[mg][nt][3] - m1);
                __half2 h01 = __floats2half2_rn(e0, e1);
                __half2 h23 = __floats2half2_rn(e2, e3);
                sp[r0][nt * 4 + tg]     = h2_bits(h01);
                sp[r0 + 8][nt * 4 + tg] = h2_bits(h23);
                float2 p01 = __half22float2(h01);
                float2 p23 = __half22float2(h23);
                L[mg][0] += p01.x + p01.y;
                L[mg][1] += p23.x + p23.y;
            }
        }
        __syncwarp();

        // ---- AV: co += P x V  (fp16 x1, m16n8k16: K = 16 j's per mma) ----
        #pragma unroll
        for (int kj = 0; kj < 2; kj++) {
            #pragma unroll
            for (int mg = 0; mg < 2; mg++) {
                uint32_t pa[4];
                const int r0 = wbase + mg * 16 + g;
                pa[0] = sp[r0][kj * 8 + tg];
                pa[1] = sp[r0 + 8][kj * 8 + tg];
                pa[2] = sp[r0][kj * 8 + tg + 4];
                pa[3] = sp[r0 + 8][kj * 8 + tg + 4];
                #pragma unroll
                for (int nt = 0; nt < 2; nt++) {
                    uint32_t b0 = sVt[nt * 8 + g][kj * 8 + tg];
                    uint32_t b1 = sVt[nt * 8 + g][kj * 8 + tg + 4];
                    mma16(co[mg][nt], pa, b0, b1);
                }
            }
        }
        // next iteration's syncthreads covers sVt/sp/ring reuse
    }

    // ---- deferred L reduction + epilogue (scale back by 2^m) ----
    #pragma unroll
    for (int mg = 0; mg < 2; mg++) {
        float F0 = ex2f(mo[mg][0]);
        float F1 = ex2f(mo[mg][1]);
        #pragma unroll
        for (int nt = 0; nt < 2; nt++) {
            co[mg][nt][0] *= F0; co[mg][nt][1] *= F0;
            co[mg][nt][2] *= F1; co[mg][nt][3] *= F1;
        }
        float s0 = L[mg][0] * F0;
        float s1 = L[mg][1] * F1;
        s0 += __shfl_xor_sync(0xffffffffu, s0, 1);
        s0 += __shfl_xor_sync(0xffffffffu, s0, 2);
        s1 += __shfl_xor_sync(0xffffffffu, s1, 1);
        s1 += __shfl_xor_sync(0xffffffffu, s1, 2);
        L[mg][0] = s0; L[mg][1] = s1;
    }

    #pragma unroll
    for (int mg = 0; mg < 2; mg++)
        #pragma unroll
        for (int nt = 0; nt < 2; nt++) {
            int r0 = i0 + wbase + mg * 16 + g;
            int c  = nt * 8 + 2 * tg;
            *reinterpret_cast<float2*>(&g_pacc[js][n][r0][c]) =
                make_float2(co[mg][nt][0], co[mg][nt][1]);
            *reinterpret_cast<float2*>(&g_pacc[js][n][r0 + 8][c]) =
                make_float2(co[mg][nt][2], co[mg][nt][3]);
        }
    if (tg == 0) {
        #pragma unroll
        for (int mg = 0; mg < 2; mg++) {
            g_pl[js][n][i0 + wbase + mg * 16 + g]     = L[mg][0];
            g_pl[js][n][i0 + wbase + mg * 16 + g + 8] = L[mg][1];
        }
    }
}

// ======================================================================
// Kernel 3: combine (unchanged).
// ======================================================================
__global__ void combine_kernel(float* __restrict__ out)
{
    const int TOT  = NB * 2 * QC * 28 * 28;
    const int gidx = blockIdx.x * blockDim.x + threadIdx.x;
    if (gidx >= TOT * 4) return;
    const int e  = gidx >> 2;
    const int px = gidx & 3;

    int pw = e % 28;
    int t  = e / 28;
    int ph = t % 28; t /= 28;
    int c  = t % (2 * QC);
    int n  = t / (2 * QC);

    const int i = (2 * ph + (px >> 1)) * 56 + 2 * pw + (px & 1);

    float num = 0.f, den = 0.f;
    #pragma unroll
    for (int s = 0; s < JSPLIT; s++) {
        num += g_pacc[s][n][i][c];
        den += g_pl[s][n][i];
    }
    float r = num / den;
    r += __shfl_xor_sync(0xffffffffu, r, 1);
    r += __shfl_xor_sync(0xffffffffu, r, 2);
    if (px == 0) out[e] = 0.25f * r;
}

// ======================================================================
extern "C" void kernel_launch(void* const* d_in, const int* in_sizes, int n_in,
                              void* d_out, int out_size)
{
    const float* x     = (const float*)d_in[0];
    const float* w     = (const float*)d_in[1];
    const float* bq    = (const float*)d_in[2];
    const float* gamma = (const float*)d_in[3];
    const float* beta  = (const float*)d_in[4];
    const float* mean  = (const float*)d_in[5];
    const float* var   = (const float*)d_in[6];
    const float* rq    = (const float*)d_in[7];
    const float* rk    = (const float*)d_in[8];
    const float* rv    = (const float*)d_in[9];
    float* out = (float*)d_out;

    dim3 g1(HWP / QPIX, NB);          // (52, 4)
    qkv_kernel<<<g1, 256>>>(x, w, bq, gamma, beta, mean, var, rq, rk, rv);

    dim3 g2(HWP / 128, JSPLIT, NB);   // (26, 14, 4)
    attn_kernel<<<g2, 128>>>();

    const int TOT = NB * 2 * QC * 28 * 28;
    combine_kernel<<<(TOT * 4 + 255) / 256, 256>>>(out);
}

// round 17
// speedup vs baseline: 1.4562x; 1.0547x over previous
#include <cuda_runtime.h>
#include <cuda_fp16.h>
#include <math.h>
#include <stdint.h>

#define NB      4
#define IN_CHAN 128
#define HW      3136
#define HWP     3328      // 26*128 = 13*256 = 52*64
#define OC      32
#define QC      8
#define D       16
#define JSPLIT  14
#define JLEN    (HW / JSPLIT)   // 224
#define TJ      32
#define NT      (JLEN / TJ)     // 7 tiles
#define BN_EPS  1e-5f
#define QPIX    64
#define LOG2E   1.44269504088896340736f

#define SB_STRIDE 20      // f32 tile rows, conflict-free

// ---------------- scratch (device globals; no allocation allowed) ----------------
__device__ __align__(16) float g_A[NB][HWP][D];                 // log2e*[q+rk ; rq]
__device__ __align__(16) float g_B[NB][HWP][D];                 // [k ; q]
__device__ __align__(16) float g_V[NB][HWP][D];                 // v + rv
__device__ __align__(16) float g_pacc[JSPLIT][NB][HWP][D];      // partial sum(e^s * v), 2^m-scaled
__device__ __align__(16) float g_pl[JSPLIT][NB][HWP];           // partial sum(e^s)

// ---------------- helpers ----------------
__device__ __forceinline__ float ex2f(float x) {
    float r; asm("ex2.approx.ftz.f32 %0, %1;" : "=f"(r) : "f"(x)); return r;
}
__device__ __forceinline__ uint32_t h2_bits(__half2 h) { return *reinterpret_cast<uint32_t*>(&h); }
__device__ __forceinline__ uint32_t pack_h2(float lo, float hi) {
    __half2 h = __floats2half2_rn(lo, hi); return h2_bits(h);
}
__device__ __forceinline__ void h2split(float2 v, uint32_t& hi, uint32_t& lo) {
    __half2 h = __floats2half2_rn(v.x, v.y);
    hi = h2_bits(h);
    float2 b = __half22float2(h);
    __half2 l = __floats2half2_rn(v.x - b.x, v.y - b.y);
    lo = h2_bits(l);
}
__device__ __forceinline__ void mma16(float* d, const uint32_t* a, uint32_t b0, uint32_t b1) {
    asm("mma.sync.aligned.m16n8k16.row.col.f32.f16.f16.f32 "
        "{%0,%1,%2,%3}, {%4,%5,%6,%7}, {%8,%9}, {%0,%1,%2,%3};"
        : "+f"(d[0]), "+f"(d[1]), "+f"(d[2]), "+f"(d[3])
        : "r"(a[0]), "r"(a[1]), "r"(a[2]), "r"(a[3]), "r"(b0), "r"(b1));
}
__device__ __forceinline__ void cpasync16(uint32_t saddr, const void* g) {
    asm volatile("cp.async.cg.shared.global [%0], [%1], 16;" :: "r"(saddr), "l"(g));
}
__device__ __forceinline__ void cpasync_commit() {
    asm volatile("cp.async.commit_group;" ::: "memory");
}
__device__ __forceinline__ void cpasync_wait1() {
    asm volatile("cp.async.wait_group 1;" ::: "memory");
}
__device__ __forceinline__ void cpasync_wait0() {
    asm volatile("cp.async.wait_group 0;" ::: "memory");
}

// ======================================================================
// Kernel 1: QKV 1x1 conv + BN + build A/B/V (unchanged, ~15.8us).
// ======================================================================
__global__ __launch_bounds__(256)
void qkv_kernel(const float* __restrict__ x, const float* __restrict__ w,
                const float* __restrict__ bq, const float* __restrict__ gamma,
                const float* __restrict__ beta, const float* __restrict__ mean,
                const float* __restrict__ var,
                const float* __restrict__ rq, const float* __restrict__ rk,
                const float* __restrict__ rv)
{
    __shared__ float sx[IN_CHAN][QPIX];
    __shared__ float sw[IN_CHAN][OC];
    __shared__ float srk[QC][QPIX];
    __shared__ float srq[QC][QPIX];
    __shared__ float srv[2 * QC][QPIX];
    __shared__ float sscale[OC], sbias[OC];
    __shared__ float sr[QPIX][OC + 1];

    const int tid = threadIdx.x;
    const int p   = tid & (QPIX - 1);
    const int qd  = tid >> 6;

    const int n    = blockIdx.y;
    const int pix0 = blockIdx.x * QPIX;
    const bool live = (pix0 < HW);

    if (live) {
        const float* xb = x + (size_t)n * IN_CHAN * HW + pix0;
        #pragma unroll
        for (int k = 0; k < 8; k++) {
            int i = k * 256 + tid;
            int c = i >> 4, j = (i & 15) * 4;
            cpasync16((uint32_t)__cvta_generic_to_shared(&sx[c][j]),
                      xb + (size_t)c * HW + j);
        }
        #pragma unroll
        for (int k = 0; k < 2; k++) {
            int i = k * 256 + tid;
            int row = i >> 4, j = (i & 15) * 4;
            const float* gsrc;
            float* sdst;
            if (row < 8)       { gsrc = rk + (size_t)row * HW + pix0 + j;        sdst = &srk[row][j]; }
            else if (row < 16) { gsrc = rq + (size_t)(row - 8) * HW + pix0 + j;  sdst = &srq[row - 8][j]; }
            else               { gsrc = rv + (size_t)(row - 16) * HW + pix0 + j; sdst = &srv[row - 16][j]; }
            cpasync16((uint32_t)__cvta_generic_to_shared(sdst), gsrc);
        }
    }

    for (int idx = tid; idx < IN_CHAN * OC; idx += 256) {
        int o = idx & (OC - 1), c = idx >> 5;
        sw[c][o] = w[o * IN_CHAN + c];
    }
    if (tid < OC) {
        float sc = gamma[tid] * rsqrtf(var[tid] + BN_EPS);
        sscale[tid] = sc;
        sbias[tid]  = (bq[tid] - mean[tid]) * sc + beta[tid];
    }

    if (live) { cpasync_commit(); cpasync_wait0(); }
    __syncthreads();

    if (live) {
        const int obase = qd * 8;
        float acc[8];
        #pragma unroll
        for (int k = 0; k < 8; k++) acc[k] = 0.f;

        #pragma unroll 4
        for (int c = 0; c < IN_CHAN; c++) {
            const float xs = sx[c][p];
            float4 wa = *reinterpret_cast<const float4*>(&sw[c][obase]);
            float4 wb = *reinterpret_cast<const float4*>(&sw[c][obase + 4]);
            acc[0] = fmaf(xs, wa.x, acc[0]);
            acc[1] = fmaf(xs, wa.y, acc[1]);
            acc[2] = fmaf(xs, wa.z, acc[2]);
            acc[3] = fmaf(xs, wa.w, acc[3]);
            acc[4] = fmaf(xs, wb.x, acc[4]);
            acc[5] = fmaf(xs, wb.y, acc[5]);
            acc[6] = fmaf(xs, wb.z, acc[6]);
            acc[7] = fmaf(xs, wb.w, acc[7]);
        }
        #pragma unroll
        for (int k = 0; k < 8; k++)
            sr[p][obase + k] = fmaf(acc[k], sscale[obase + k], sbias[obase + k]);
    }
    __syncthreads();

    const int gpix = pix0 + p;
    if (live) {
        if (qd == 0) {
            float av[8];
            #pragma unroll
            for (int c = 0; c < 8; c++)
                av[c] = LOG2E * (sr[p][c] + srk[c][p]);
            reinterpret_cast<float4*>(&g_A[n][gpix][0])[0] = reinterpret_cast<float4*>(av)[0];
            reinterpret_cast<float4*>(&g_A[n][gpix][0])[1] = reinterpret_cast<float4*>(av)[1];
        } else if (qd == 1) {
            float av[8];
            #pragma unroll
            for (int c = 0; c < 8; c++)
                av[c] = LOG2E * srq[c][p];
            reinterpret_cast<float4*>(&g_A[n][gpix][8])[0] = reinterpret_cast<float4*>(av)[0];
            reinterpret_cast<float4*>(&g_A[n][gpix][8])[1] = reinterpret_cast<float4*>(av)[1];
        } else if (qd == 2) {
            float bv[16];
            #pragma unroll
            for (int c = 0; c < 8; c++) { bv[c] = sr[p][QC + c]; bv[QC + c] = sr[p][c]; }
            #pragma unroll
            for (int q4 = 0; q4 < 4; q4++)
                reinterpret_cast<float4*>(&g_B[n][gpix][0])[q4] = reinterpret_cast<float4*>(bv)[q4];
        } else {
            float vv[16];
            #pragma unroll
            for (int c = 0; c < 16; c++)
                vv[c] = sr[p][2 * QC + c] + srv[c][p];
            #pragma unroll
            for (int q4 = 0; q4 < 4; q4++)
                reinterpret_cast<float4*>(&g_V[n][gpix][0])[q4] = reinterpret_cast<float4*>(vv)[q4];
        }
    } else {
        float4 z = make_float4(0.f, 0.f, 0.f, 0.f);
        if (qd == 0) {
            reinterpret_cast<float4*>(&g_A[n][gpix][0])[0] = z;
            reinterpret_cast<float4*>(&g_A[n][gpix][0])[1] = z;
        } else if (qd == 1) {
            reinterpret_cast<float4*>(&g_A[n][gpix][8])[0] = z;
            reinterpret_cast<float4*>(&g_A[n][gpix][8])[1] = z;
        } else if (qd == 2) {
            #pragma unroll
            for (int q4 = 0; q4 < 4; q4++)
                reinterpret_cast<float4*>(&g_B[n][gpix][0])[q4] = z;
        } else {
            #pragma unroll
            for (int q4 = 0; q4 < 4; q4++)
                reinterpret_cast<float4*>(&g_V[n][gpix][0])[q4] = z;
        }
    }
}

// ======================================================================
// Kernel 2: fp16 m16n8k16 attention, REGISTER-RESIDENT P.
// Key fact: the PV A-fragment {row g,k-lo | row g+8,k-lo | row g,k-hi |
// row g+8,k-hi} for kj is exactly {h01[2kj], h23[2kj], h01[2kj+1],
// h23[2kj+1]} — the same thread's score outputs. No sp smem, no sVt,
// ONE barrier per tile (ring guard only).
//   scores: fp16 x3   softmax: online max (2^m folded in epilogue)
//   PV: fp16 x1, l summed over the same rounded P the mma consumes
// ======================================================================
__global__ __launch_bounds__(128, 4)
void attn_kernel()
{
    __shared__ __align__(16) float sB[3][TJ][SB_STRIDE];     // raw B ring (f32)
    __shared__ __align__(16) float sV[3][TJ][SB_STRIDE];     // raw V ring (f32)

    const int tid   = threadIdx.x;
    const int warp  = tid >> 5;
    const int lane  = tid & 31;
    const int g     = lane >> 2;
    const int tg    = lane & 3;
    const int itile = blockIdx.x;
    const int js    = blockIdx.y;
    const int n     = blockIdx.z;
    const int i0    = itile * 128;
    const int wbase = warp * 32;
    const int jbase = js * JLEN;

    const int lr  = tid >> 2;           // ring-load row
    const int lc4 = (tid & 3) * 4;      // ring-load col chunk

    // ---- persistent A fragments (f16 hi/lo, m16n8k16 A layout) ----
    uint32_t ahh[2][4], ahl[2][4];
    #pragma unroll
    for (int mg = 0; mg < 2; mg++) {
        #pragma unroll
        for (int r = 0; r < 4; r++) {
            int row = i0 + wbase + mg * 16 + g + ((r & 1) ? 8 : 0);
            int col = 2 * tg + ((r & 2) ? 8 : 0);
            float2 a2 = *reinterpret_cast<const float2*>(&g_A[n][row][col]);
            h2split(a2, ahh[mg][r], ahl[mg][r]);
        }
    }

    float co[2][2][4];
    #pragma unroll
    for (int mg = 0; mg < 2; mg++)
        #pragma unroll
        for (int nt = 0; nt < 2; nt++)
            #pragma unroll
            for (int r = 0; r < 4; r++) co[mg][nt][r] = 0.f;
    float L[2][2]  = {{0.f, 0.f}, {0.f, 0.f}};
    float mo[2][2] = {{-1e30f, -1e30f}, {-1e30f, -1e30f}};  // running row max (log2)

    // ---- prolog: issue tile 0 ----
    {
        cpasync16((uint32_t)__cvta_generic_to_shared(&sB[0][lr][lc4]),
                  &g_B[n][jbase + lr][lc4]);
        cpasync16((uint32_t)__cvta_generic_to_shared(&sV[0][lr][lc4]),
                  &g_V[n][jbase + lr][lc4]);
        cpasync_commit();
    }

    for (int t = 0; t < NT; t++) {
        if (t + 1 < NT) {
            const int jn = jbase + (t + 1) * TJ;
            const int nb = (t + 1) % 3;
            cpasync16((uint32_t)__cvta_generic_to_shared(&sB[nb][lr][lc4]),
                      &g_B[n][jn + lr][lc4]);
            cpasync16((uint32_t)__cvta_generic_to_shared(&sV[nb][lr][lc4]),
                      &g_V[n][jn + lr][lc4]);
            cpasync_commit();
            cpasync_wait1();
        } else {
            cpasync_wait0();
        }
        __syncthreads();          // the ONLY barrier in the tile loop
        const int buf = t % 3;

        // ---- scores: S[32i x 32j] per warp, fp16 x3, split at read ----
        float cs[2][4][4];
        #pragma unroll
        for (int mg = 0; mg < 2; mg++)
            #pragma unroll
            for (int nt = 0; nt < 4; nt++)
                #pragma unroll
                for (int r = 0; r < 4; r++) cs[mg][nt][r] = 0.f;

        #pragma unroll
        for (int nt = 0; nt < 4; nt++) {
            float2 q0 = *reinterpret_cast<const float2*>(&sB[buf][nt * 8 + g][2 * tg]);
            float2 q1 = *reinterpret_cast<const float2*>(&sB[buf][nt * 8 + g][2 * tg + 8]);
            uint32_t bh0, bl0, bh1, bl1;
            h2split(q0, bh0, bl0);
            h2split(q1, bh1, bl1);
            #pragma unroll
            for (int mg = 0; mg < 2; mg++) {
                mma16(cs[mg][nt], ahh[mg], bh0, bh1);
                mma16(cs[mg][nt], ahl[mg], bh0, bh1);
                mma16(cs[mg][nt], ahh[mg], bl0, bl1);
            }
        }

        // ---- online max + rescale + exp2 -> register-resident f16 P ----
        uint32_t ph[2][4][2];     // [mg][nt][0]=rows g / [1]=rows g+8 (f16x2 j-pair)
        #pragma unroll
        for (int mg = 0; mg < 2; mg++) {
            float m0t = fmaxf(cs[mg][0][0], cs[mg][0][1]);
            float m1t = fmaxf(cs[mg][0][2], cs[mg][0][3]);
            #pragma unroll
            for (int nt = 1; nt < 4; nt++) {
                m0t = fmaxf(m0t, fmaxf(cs[mg][nt][0], cs[mg][nt][1]));
                m1t = fmaxf(m1t, fmaxf(cs[mg][nt][2], cs[mg][nt][3]));
            }
            m0t = fmaxf(m0t, __shfl_xor_sync(0xffffffffu, m0t, 1));
            m0t = fmaxf(m0t, __shfl_xor_sync(0xffffffffu, m0t, 2));
            m1t = fmaxf(m1t, __shfl_xor_sync(0xffffffffu, m1t, 1));
            m1t = fmaxf(m1t, __shfl_xor_sync(0xffffffffu, m1t, 2));
            float m0 = fmaxf(mo[mg][0], m0t);
            float m1 = fmaxf(mo[mg][1], m1t);
            float f0 = ex2f(mo[mg][0] - m0);
            float f1 = ex2f(mo[mg][1] - m1);
            mo[mg][0] = m0; mo[mg][1] = m1;
            #pragma unroll
            for (int nt = 0; nt < 2; nt++) {
                co[mg][nt][0] *= f0; co[mg][nt][1] *= f0;
                co[mg][nt][2] *= f1; co[mg][nt][3] *= f1;
            }
            L[mg][0] *= f0; L[mg][1] *= f1;

            #pragma unroll
            for (int nt = 0; nt < 4; nt++) {
                float e0 = ex2f(cs[mg][nt][0] - m0);
                float e1 = ex2f(cs[mg][nt][1] - m0);
                float e2 = ex2f(cs[mg][nt][2] - m1);
                float e3 = ex2f(cs[mg][nt][3] - m1);
                __half2 h01 = __floats2half2_rn(e0, e1);
                __half2 h23 = __floats2half2_rn(e2, e3);
                ph[mg][nt][0] = h2_bits(h01);
                ph[mg][nt][1] = h2_bits(h23);
                float2 p01 = __half22float2(h01);
                float2 p23 = __half22float2(h23);
                L[mg][0] += p01.x + p01.y;
                L[mg][1] += p23.x + p23.y;
            }
        }

        // ---- AV: co += P x V; P from OWN registers, V packed from raw sV ----
        #pragma unroll
        for (int kj = 0; kj < 2; kj++) {
            uint32_t vb0[2], vb1[2];
            const int j0 = kj * 16 + 2 * tg;
            #pragma unroll
            for (int nt = 0; nt < 2; nt++) {
                const int d = nt * 8 + g;
                vb0[nt] = pack_h2(sV[buf][j0][d],     sV[buf][j0 + 1][d]);
                vb1[nt] = pack_h2(sV[buf][j0 + 8][d], sV[buf][j0 + 9][d]);
            }
            #pragma unroll
            for (int mg = 0; mg < 2; mg++) {
                uint32_t pa[4] = { ph[mg][2 * kj][0],     ph[mg][2 * kj][1],
                                   ph[mg][2 * kj + 1][0], ph[mg][2 * kj + 1][1] };
                #pragma unroll
                for (int nt = 0; nt < 2; nt++)
                    mma16(co[mg][nt], pa, vb0[nt], vb1[nt]);
            }
        }
    }

    // ---- deferred L reduction + epilogue (scale back by 2^m) ----
    #pragma unroll
    for (int mg = 0; mg < 2; mg++) {
        float F0 = ex2f(mo[mg][0]);
        float F1 = ex2f(mo[mg][1]);
        #pragma unroll
        for (int nt = 0; nt < 2; nt++) {
            co[mg][nt][0] *= F0; co[mg][nt][1] *= F0;
            co[mg][nt][2] *= F1; co[mg][nt][3] *= F1;
        }
        float s0 = L[mg][0] * F0;
        float s1 = L[mg][1] * F1;
        s0 += __shfl_xor_sync(0xffffffffu, s0, 1);
        s0 += __shfl_xor_sync(0xffffffffu, s0, 2);
        s1 += __shfl_xor_sync(0xffffffffu, s1, 1);
        s1 += __shfl_xor_sync(0xffffffffu, s1, 2);
        L[mg][0] = s0; L[mg][1] = s1;
    }

    #pragma unroll
    for (int mg = 0; mg < 2; mg++)
        #pragma unroll
        for (int nt = 0; nt < 2; nt++) {
            int r0 = i0 + wbase + mg * 16 + g;
            int c  = nt * 8 + 2 * tg;
            *reinterpret_cast<float2*>(&g_pacc[js][n][r0][c]) =
                make_float2(co[mg][nt][0], co[mg][nt][1]);
            *reinterpret_cast<float2*>(&g_pacc[js][n][r0 + 8][c]) =
                make_float2(co[mg][nt][2], co[mg][nt][3]);
        }
    if (tg == 0) {
        #pragma unroll
        for (int mg = 0; mg < 2; mg++) {
            g_pl[js][n][i0 + wbase + mg * 16 + g]     = L[mg][0];
            g_pl[js][n][i0 + wbase + mg * 16 + g + 8] = L[mg][1];
        }
    }
}

// ======================================================================
// Kernel 3: combine (unchanged).
// ======================================================================
__global__ void combine_kernel(float* __restrict__ out)
{
    const int TOT  = NB * 2 * QC * 28 * 28;
    const int gidx = blockIdx.x * blockDim.x + threadIdx.x;
    if (gidx >= TOT * 4) return;
    const int e  = gidx >> 2;
    const int px = gidx & 3;

    int pw = e % 28;
    int t  = e / 28;
    int ph = t % 28; t /= 28;
    int c  = t % (2 * QC);
    int n  = t / (2 * QC);

    const int i = (2 * ph + (px >> 1)) * 56 + 2 * pw + (px & 1);

    float num = 0.f, den = 0.f;
    #pragma unroll
    for (int s = 0; s < JSPLIT; s++) {
        num += g_pacc[s][n][i][c];
        den += g_pl[s][n][i];
    }
    float r = num / den;
    r += __shfl_xor_sync(0xffffffffu, r, 1);
    r += __shfl_xor_sync(0xffffffffu, r, 2);
    if (px == 0) out[e] = 0.25f * r;
}

// ======================================================================
extern "C" void kernel_launch(void* const* d_in, const int* in_sizes, int n_in,
                              void* d_out, int out_size)
{
    const float* x     = (const float*)d_in[0];
    const float* w     = (const float*)d_in[1];
    const float* bq    = (const float*)d_in[2];
    const float* gamma = (const float*)d_in[3];
    const float* beta  = (const float*)d_in[4];
    const float* mean  = (const float*)d_in[5];
    const float* var   = (const float*)d_in[6];
    const float* rq    = (const float*)d_in[7];
    const float* rk    = (const float*)d_in[8];
    const float* rv    = (const float*)d_in[9];
    float* out = (float*)d_out;

    dim3 g1(HWP / QPIX, NB);          // (52, 4)
    qkv_kernel<<<g1, 256>>>(x, w, bq, gamma, beta, mean, var, rq, rk, rv);

    dim3 g2(HWP / 128, JSPLIT, NB);   // (26, 14, 4)
    attn_kernel<<<g2, 128>>>();

    const int TOT = NB * 2 * QC * 28 * 28;
    combine_kernel<<<(TOT * 4 + 255) / 256, 256>>>(out);
}